// round 5
// baseline (speedup 1.0000x reference)
#include <cuda_runtime.h>
#include <cuda_bf16.h>
#include <cstdint>

#define NCH   16
#define NPAIR 256
#define DIMK  128
#define NB    131072
#define TPP   2
#define TSTRIDE 272

// ---- k_main smem layout ----
// Prologue reuses S_AHI..(S_AHI+34816) as the 128-row E_d tile, S_B as E_e rows then E.
#define S_BIAS   0
#define S_PERM   512
#define S_STAGE  1024                         // 64 x 512B fp32 stage
#define S_AHI    (S_STAGE + 64 * 512)         // 33792
#define S_ALO    (S_AHI + 64 * TSTRIDE)
#define S_B      (S_ALO + 64 * TSTRIDE)
#define MAIN_SMEM (S_B + 128 * TSTRIDE)       // ~103.4 KB -> 2 CTAs/SM

// ---- scratch ----
__device__ int g_perm[NB];
__device__ int g_count[NPAIR];
__device__ int g_offset[NPAIR];
__device__ int g_cursor[NPAIR];

// ------------------------------ helpers ------------------------------
static __device__ __forceinline__ uint32_t smem_u32(const void* p) {
    uint32_t a;
    asm("{ .reg .u64 t; cvta.to.shared.u64 t, %1; cvt.u32.u64 %0, t; }" : "=r"(a) : "l"(p));
    return a;
}
static __device__ __forceinline__ void split4(float4 v, uint2& hi, uint2& lo) {
    __nv_bfloat162 h01 = __floats2bfloat162_rn(v.x, v.y);
    __nv_bfloat162 h23 = __floats2bfloat162_rn(v.z, v.w);
    float2 f01 = __bfloat1622float2(h01);
    float2 f23 = __bfloat1622float2(h23);
    __nv_bfloat162 l01 = __floats2bfloat162_rn(v.x - f01.x, v.y - f01.y);
    __nv_bfloat162 l23 = __floats2bfloat162_rn(v.z - f23.x, v.w - f23.y);
    hi.x = reinterpret_cast<uint32_t&>(h01); hi.y = reinterpret_cast<uint32_t&>(h23);
    lo.x = reinterpret_cast<uint32_t&>(l01); lo.y = reinterpret_cast<uint32_t&>(l23);
}
static __device__ __forceinline__ void ldsm_x4(uint32_t* r, uint32_t a) {
    asm volatile("ldmatrix.sync.aligned.m8n8.x4.shared.b16 {%0,%1,%2,%3}, [%4];"
        : "=r"(r[0]), "=r"(r[1]), "=r"(r[2]), "=r"(r[3]) : "r"(a));
}
static __device__ __forceinline__ void ldsm_x4t(uint32_t* r, uint32_t a) {
    asm volatile("ldmatrix.sync.aligned.m8n8.x4.trans.shared.b16 {%0,%1,%2,%3}, [%4];"
        : "=r"(r[0]), "=r"(r[1]), "=r"(r[2]), "=r"(r[3]) : "r"(a));
}
static __device__ __forceinline__ void mma_bf16(float* d, const uint32_t* a, const uint32_t* b) {
    asm volatile(
        "mma.sync.aligned.m16n8k16.row.col.f32.bf16.bf16.f32 "
        "{%0,%1,%2,%3}, {%4,%5,%6,%7}, {%8,%9}, {%0,%1,%2,%3};"
        : "+f"(d[0]), "+f"(d[1]), "+f"(d[2]), "+f"(d[3])
        : "r"(a[0]), "r"(a[1]), "r"(a[2]), "r"(a[3]), "r"(b[0]), "r"(b[1]));
}
static __device__ __forceinline__ void cpasync16(uint32_t dst, const void* src) {
    asm volatile("cp.async.ca.shared.global [%0], [%1], 16;" :: "r"(dst), "l"(src));
}

// ------------------------------ sort ------------------------------
__global__ void k_init() { g_count[threadIdx.x] = 0; }

__global__ void k_hist(const int* __restrict__ src, const int* __restrict__ tgt) {
    __shared__ int h[NPAIR];
    int t = threadIdx.x;
    h[t] = 0;
    __syncthreads();
    for (int i = blockIdx.x * blockDim.x + t; i < NB; i += gridDim.x * blockDim.x) {
        int p = ((src[i] & 15) << 4) | (tgt[i] & 15);
        atomicAdd(&h[p], 1);
    }
    __syncthreads();
    atomicAdd(&g_count[t], h[t]);
}

__global__ void k_scan() {
    __shared__ int s[NPAIR];
    int t = threadIdx.x;
    s[t] = g_count[t];
    __syncthreads();
    for (int d = 1; d < NPAIR; d <<= 1) {
        int add = (t >= d) ? s[t - d] : 0;
        __syncthreads();
        s[t] += add;
        __syncthreads();
    }
    int excl = (t == 0) ? 0 : s[t - 1];
    g_offset[t] = excl;
    g_cursor[t] = excl;
}

__global__ void k_scatter(const int* __restrict__ src, const int* __restrict__ tgt) {
    __shared__ int h[NPAIR], base[NPAIR];
    __shared__ unsigned char code[2048];
    int t = threadIdx.x;
    h[t] = 0;
    __syncthreads();
    int lo = blockIdx.x * 2048;
    for (int j = t; j < 2048; j += 256) {
        int i = lo + j;
        int p = ((src[i] & 15) << 4) | (tgt[i] & 15);
        code[j] = (unsigned char)p;
        atomicAdd(&h[p], 1);
    }
    __syncthreads();
    base[t] = atomicAdd(&g_cursor[t], h[t]);
    h[t] = 0;
    __syncthreads();
    for (int j = t; j < 2048; j += 256) {
        int p = code[j];
        int r = atomicAdd(&h[p], 1);
        g_perm[base[p] + r] = lo + j;
    }
}

// ------------------------------ fused main GEMM ------------------------------
// Prologue per CTA: compute E = dec@enc - I = E_d + E_e + E_d@E_e into smem B tile,
// bias = dec@c + d into smem. Then: out[row,:] = z + z@E^T + bias, rows grouped by pair.
__global__ void __launch_bounds__(256, 2)
k_main(const float* __restrict__ Z, float* __restrict__ Y,
       const float* __restrict__ enc, const float* __restrict__ dec,
       const float* __restrict__ cpar, const float* __restrict__ dpar) {
    extern __shared__ char smem[];
    uint32_t sb = smem_u32(smem);
    int tid = threadIdx.x, wid = tid >> 5, lane = tid & 31;
    int p = blockIdx.x / TPP, t0 = blockIdx.x % TPP;
    int s = p >> 4, tch = p & 15;

    int cnt = g_count[p], off = g_offset[p];
    if (t0 * 64 >= cnt) return;

    float* sbias = (float*)(smem + S_BIAS);
    int*   sperm = (int*)(smem + S_PERM);

    // ---- kick off stage-0 gather before prologue (hides DRAM latency) ----
    {
        int base = off + t0 * 64;
        int rows = cnt - t0 * 64; if (rows > 64) rows = 64;
        #pragma unroll
        for (int it = 0; it < 8; it++) {
            int idx = it * 256 + tid;
            int r = idx >> 5, c4 = idx & 31;
            int rr = (r < rows) ? r : 0;
            int grow = __ldg(&g_perm[base + rr]);
            cpasync16(sb + S_STAGE + r * 512 + c4 * 16, Z + (size_t)grow * DIMK + c4 * 4);
        }
        asm volatile("cp.async.commit_group;");
    }

    const float* decT = dec + (size_t)tch * DIMK * DIMK;
    const float* encS = enc + (size_t)s * DIMK * DIMK;

    // ---- prologue: build E in S_B ----
    // E_d = dec - I  -> 128-row bf16 tile at S_AHI (row-major [i][k])
    {
        const float4* d4 = (const float4*)decT;
        #pragma unroll
        for (int it = 0; it < 16; it++) {
            int idx = it * 256 + tid;
            int d = idx >> 5, r4 = idx & 31;
            float4 v = __ldg(d4 + idx);
            int rb = r4 * 4;
            if (d == rb + 0) v.x -= 1.f;
            if (d == rb + 1) v.y -= 1.f;
            if (d == rb + 2) v.z -= 1.f;
            if (d == rb + 3) v.w -= 1.f;
            __nv_bfloat162 b01 = __floats2bfloat162_rn(v.x, v.y);
            __nv_bfloat162 b23 = __floats2bfloat162_rn(v.z, v.w);
            uint2 u; u.x = reinterpret_cast<uint32_t&>(b01); u.y = reinterpret_cast<uint32_t&>(b23);
            *(uint2*)(smem + S_AHI + d * TSTRIDE + r4 * 8) = u;
        }
    }
    // E_e = enc - I  -> ROW-major [k][n] bf16 at S_B (conflict-free; loaded via ldsm.trans)
    {
        const float4* e4 = (const float4*)encS;
        #pragma unroll
        for (int it = 0; it < 16; it++) {
            int idx = it * 256 + tid;
            int r = idx >> 5, c4 = idx & 31;
            float4 v = __ldg(e4 + idx);
            int cb = c4 * 4;
            if (r == cb + 0) v.x -= 1.f;
            if (r == cb + 1) v.y -= 1.f;
            if (r == cb + 2) v.z -= 1.f;
            if (r == cb + 3) v.w -= 1.f;
            __nv_bfloat162 b01 = __floats2bfloat162_rn(v.x, v.y);
            __nv_bfloat162 b23 = __floats2bfloat162_rn(v.z, v.w);
            uint2 u; u.x = reinterpret_cast<uint32_t&>(b01); u.y = reinterpret_cast<uint32_t&>(b23);
            *(uint2*)(smem + S_B + r * TSTRIDE + c4 * 8) = u;
        }
    }
    __syncthreads();

    // E_d @ E_e : 8 warps = 4(M) x 2(N), each 32 x 64
    {
        int wm = wid & 3, wn = wid >> 2;
        float pacc[2][8][4];
        #pragma unroll
        for (int mt = 0; mt < 2; mt++)
            #pragma unroll
            for (int nt = 0; nt < 8; nt++)
                #pragma unroll
                for (int i = 0; i < 4; i++) pacc[mt][nt][i] = 0.f;

        #pragma unroll
        for (int ks = 0; ks < 8; ks++) {
            int kb = ks * 16;
            uint32_t a[2][4];
            #pragma unroll
            for (int mt = 0; mt < 2; mt++) {
                uint32_t row = wm * 32 + mt * 16 + (lane & 15);
                ldsm_x4(a[mt], sb + S_AHI + row * TSTRIDE + kb * 2 + ((lane >> 4) << 4));
            }
            #pragma unroll
            for (int j = 0; j < 4; j++) {
                uint32_t n0 = wn * 64 + j * 16;
                // trans-ldsm from row-major [k][n]: rows k, col n0 (+8 per lane>>3)
                uint32_t adr = sb + S_B
                    + (kb + (lane & 7) + ((lane >> 4) & 1) * 8) * TSTRIDE
                    + (n0 + ((lane >> 3) & 1) * 8) * 2;
                uint32_t q[4];
                ldsm_x4t(q, adr);
                uint32_t b0[2] = {q[0], q[2]}, b1[2] = {q[1], q[3]};
                #pragma unroll
                for (int mt = 0; mt < 2; mt++) {
                    mma_bf16(pacc[mt][j * 2 + 0], a[mt], b0);
                    mma_bf16(pacc[mt][j * 2 + 1], a[mt], b1);
                }
            }
        }
        __syncthreads();   // all trans reads of S_B done before overwrite

        // pack E = pacc + dec + enc - 2I  into S_B rows [i][k]
        int gid = lane >> 2, tig = lane & 3;
        #pragma unroll
        for (int mt = 0; mt < 2; mt++) {
            #pragma unroll
            for (int nt = 0; nt < 8; nt++) {
                int j = wn * 64 + nt * 8 + tig * 2;
                #pragma unroll
                for (int half = 0; half < 2; half++) {
                    int i = wm * 32 + mt * 16 + gid + half * 8;
                    float2 dv = *(const float2*)(decT + i * DIMK + j);
                    float2 ev = *(const float2*)(encS + i * DIMK + j);
                    float w0 = pacc[mt][nt][half * 2 + 0] + dv.x + ev.x - (i == j     ? 2.f : 0.f);
                    float w1 = pacc[mt][nt][half * 2 + 1] + dv.y + ev.y - (i == j + 1 ? 2.f : 0.f);
                    *(__nv_bfloat162*)(smem + S_B + i * TSTRIDE + j * 2) = __floats2bfloat162_rn(w0, w1);
                }
            }
        }
    }

    // bias = dec @ c + d
    if (tid < DIMK) {
        const float4* drow = (const float4*)(decT + tid * DIMK);
        const float4* cv4  = (const float4*)(cpar + s * DIMK);
        float b = dpar[tch * DIMK + tid];
        #pragma unroll
        for (int r4 = 0; r4 < 32; r4++) {
            float4 w = __ldg(drow + r4);
            float4 c = __ldg(cv4 + r4);
            b += w.x * c.x + w.y * c.y + w.z * c.z + w.w * c.w;
        }
        sbias[tid] = b;
    }
    __syncthreads();

    // ---- main loop ----
    int wm = wid & 1, wn = wid >> 1;
    for (int t = t0; t * 64 < cnt; t += TPP) {
        int base = off + t * 64;
        int rows = cnt - t * 64; if (rows > 64) rows = 64;

        asm volatile("cp.async.wait_group 0;" ::: "memory");
        __syncthreads();   // stage ready; prior-iter epilogue reads done

        if (tid < 64) sperm[tid] = g_perm[base + ((tid < rows) ? tid : 0)];

        // convert stage fp32 -> split bf16 A tiles
        #pragma unroll
        for (int it = 0; it < 8; it++) {
            int idx = it * 256 + tid;
            int r = idx >> 5, c4 = idx & 31;
            float4 v = *(const float4*)(smem + S_STAGE + r * 512 + c4 * 16);
            uint2 hi, lo; split4(v, hi, lo);
            *(uint2*)(smem + S_AHI + r * TSTRIDE + c4 * 8) = hi;
            *(uint2*)(smem + S_ALO + r * TSTRIDE + c4 * 8) = lo;
        }
        __syncthreads();

        // prefetch next tile (overlaps MMA + epilogue)
        int tn = t + TPP;
        if (tn * 64 < cnt) {
            int basen = off + tn * 64;
            int rowsn = cnt - tn * 64; if (rowsn > 64) rowsn = 64;
            #pragma unroll
            for (int it = 0; it < 8; it++) {
                int idx = it * 256 + tid;
                int r = idx >> 5, c4 = idx & 31;
                int rr = (r < rowsn) ? r : 0;
                int grow = __ldg(&g_perm[basen + rr]);
                cpasync16(sb + S_STAGE + r * 512 + c4 * 16, Z + (size_t)grow * DIMK + c4 * 4);
            }
            asm volatile("cp.async.commit_group;");
        }

        // MMA: 2 chains (z_hi, z_lo) x 8 k-steps
        float acc[2][4][4];
        #pragma unroll
        for (int mt = 0; mt < 2; mt++)
            #pragma unroll
            for (int nt = 0; nt < 4; nt++)
                #pragma unroll
                for (int i = 0; i < 4; i++) acc[mt][nt][i] = 0.f;

        #pragma unroll
        for (int ks = 0; ks < 8; ks++) {
            int kb = ks * 16;
            uint32_t ah[2][4], al[2][4];
            #pragma unroll
            for (int mt = 0; mt < 2; mt++) {
                uint32_t row = wm * 32 + mt * 16 + (lane & 15);
                uint32_t o = row * TSTRIDE + kb * 2 + ((lane >> 4) << 4);
                ldsm_x4(ah[mt], sb + S_AHI + o);
                ldsm_x4(al[mt], sb + S_ALO + o);
            }
            #pragma unroll
            for (int j = 0; j < 2; j++) {
                uint32_t n = wn * 32 + j * 16 + (lane & 15);
                uint32_t o = n * TSTRIDE + kb * 2 + ((lane >> 4) << 4);
                uint32_t qh[4];
                ldsm_x4(qh, sb + S_B + o);
                uint32_t b0[2] = {qh[0], qh[2]}, b1[2] = {qh[1], qh[3]};
                #pragma unroll
                for (int mt = 0; mt < 2; mt++) {
                    mma_bf16(acc[mt][j * 2 + 0], ah[mt], b0);
                    mma_bf16(acc[mt][j * 2 + 0], al[mt], b0);
                    mma_bf16(acc[mt][j * 2 + 1], ah[mt], b1);
                    mma_bf16(acc[mt][j * 2 + 1], al[mt], b1);
                }
            }
        }

        // epilogue: out = acc + z (hi+lo) + bias; scatter
        int gid = lane >> 2, tig = lane & 3;
        #pragma unroll
        for (int mt = 0; mt < 2; mt++) {
            int m0 = wm * 32 + mt * 16 + gid;
            #pragma unroll
            for (int half = 0; half < 2; half++) {
                int m = m0 + half * 8;
                if (m >= rows) continue;
                long gr = (long)sperm[m];
                #pragma unroll
                for (int nt = 0; nt < 4; nt++) {
                    int n = wn * 32 + nt * 8 + tig * 2;
                    __nv_bfloat162 zh = *(const __nv_bfloat162*)(smem + S_AHI + m * TSTRIDE + n * 2);
                    __nv_bfloat162 zl = *(const __nv_bfloat162*)(smem + S_ALO + m * TSTRIDE + n * 2);
                    float2 zhf = __bfloat1622float2(zh);
                    float2 zlf = __bfloat1622float2(zl);
                    float2 o;
                    o.x = acc[mt][nt][half * 2 + 0] + zhf.x + zlf.x + sbias[n];
                    o.y = acc[mt][nt][half * 2 + 1] + zhf.y + zlf.y + sbias[n + 1];
                    *(float2*)(Y + gr * DIMK + n) = o;
                }
            }
        }
    }
}

// ------------------------------ launch ------------------------------
extern "C" void kernel_launch(void* const* d_in, const int* in_sizes, int n_in,
                              void* d_out, int out_size) {
    const float* z    = (const float*)d_in[0];
    const int*   src  = (const int*)  d_in[1];
    const int*   tgt  = (const int*)  d_in[2];
    const float* enc  = (const float*)d_in[3];
    const float* dec  = (const float*)d_in[4];
    const float* cpar = (const float*)d_in[5];
    const float* dpar = (const float*)d_in[6];
    float* out = (float*)d_out;

    cudaFuncSetAttribute(k_main, cudaFuncAttributeMaxDynamicSharedMemorySize, MAIN_SMEM);

    k_init<<<1, 256>>>();
    k_hist<<<256, 256>>>(src, tgt);
    k_scan<<<1, 256>>>();
    k_scatter<<<NB / 2048, 256>>>(src, tgt);
    k_main<<<NPAIR * TPP, 256, MAIN_SMEM>>>(z, out, enc, dec, cpar, dpar);
}

// round 6
// speedup vs baseline: 1.1267x; 1.1267x over previous
#include <cuda_runtime.h>
#include <cuda_bf16.h>
#include <cstdint>

#define NCH   16
#define NPAIR 256
#define DIMK  128
#define NB    131072
#define TPP   2
#define HCTA  64                              // histogram/scatter CTAs (2048 rows each)
#define TSTRIDE 272

// ---- k_main smem layout ----
#define S_BIAS   0
#define S_PERM   512
#define S_STAGE  1024                         // 64 x 512B fp32 stage
#define S_AHI    (S_STAGE + 64 * 512)
#define S_ALO    (S_AHI + 64 * TSTRIDE)
#define S_B      (S_ALO + 64 * TSTRIDE)
#define MAIN_SMEM (S_B + 128 * TSTRIDE)       // ~103.4 KB -> 2 CTAs/SM

// ---- precompute smem layout ----
#define P_A     0
#define P_B     (128 * TSTRIDE)
#define PRE_SMEM (2 * 128 * TSTRIDE)          // 69632 B

// ---- scratch ----
__device__ __align__(16) __nv_bfloat16 g_E[(size_t)NPAIR * DIMK * DIMK];  // Wc - I
__device__ float g_bias[NPAIR * DIMK];
__device__ int   g_perm[NB];
__device__ int   g_histcta[HCTA * NPAIR];
__device__ int   g_base[HCTA * NPAIR];
__device__ int   g_count[NPAIR];
__device__ int   g_offset[NPAIR];

// ------------------------------ helpers ------------------------------
static __device__ __forceinline__ uint32_t smem_u32(const void* p) {
    uint32_t a;
    asm("{ .reg .u64 t; cvta.to.shared.u64 t, %1; cvt.u32.u64 %0, t; }" : "=r"(a) : "l"(p));
    return a;
}
static __device__ __forceinline__ void split4(float4 v, uint2& hi, uint2& lo) {
    __nv_bfloat162 h01 = __floats2bfloat162_rn(v.x, v.y);
    __nv_bfloat162 h23 = __floats2bfloat162_rn(v.z, v.w);
    float2 f01 = __bfloat1622float2(h01);
    float2 f23 = __bfloat1622float2(h23);
    __nv_bfloat162 l01 = __floats2bfloat162_rn(v.x - f01.x, v.y - f01.y);
    __nv_bfloat162 l23 = __floats2bfloat162_rn(v.z - f23.x, v.w - f23.y);
    hi.x = reinterpret_cast<uint32_t&>(h01); hi.y = reinterpret_cast<uint32_t&>(h23);
    lo.x = reinterpret_cast<uint32_t&>(l01); lo.y = reinterpret_cast<uint32_t&>(l23);
}
static __device__ __forceinline__ void ldsm_x4(uint32_t* r, uint32_t a) {
    asm volatile("ldmatrix.sync.aligned.m8n8.x4.shared.b16 {%0,%1,%2,%3}, [%4];"
        : "=r"(r[0]), "=r"(r[1]), "=r"(r[2]), "=r"(r[3]) : "r"(a));
}
static __device__ __forceinline__ void ldsm_x4t(uint32_t* r, uint32_t a) {
    asm volatile("ldmatrix.sync.aligned.m8n8.x4.trans.shared.b16 {%0,%1,%2,%3}, [%4];"
        : "=r"(r[0]), "=r"(r[1]), "=r"(r[2]), "=r"(r[3]) : "r"(a));
}
static __device__ __forceinline__ void mma_bf16(float* d, const uint32_t* a, const uint32_t* b) {
    asm volatile(
        "mma.sync.aligned.m16n8k16.row.col.f32.bf16.bf16.f32 "
        "{%0,%1,%2,%3}, {%4,%5,%6,%7}, {%8,%9}, {%0,%1,%2,%3};"
        : "+f"(d[0]), "+f"(d[1]), "+f"(d[2]), "+f"(d[3])
        : "r"(a[0]), "r"(a[1]), "r"(a[2]), "r"(a[3]), "r"(b[0]), "r"(b[1]));
}
static __device__ __forceinline__ void cpasync16(uint32_t dst, const void* src) {
    asm volatile("cp.async.ca.shared.global [%0], [%1], 16;" :: "r"(dst), "l"(src));
}

// ------------------------------ 1: per-CTA histogram (no global atomics) -------------
__global__ void k_hist(const int* __restrict__ src, const int* __restrict__ tgt) {
    __shared__ int h[NPAIR];
    int t = threadIdx.x;
    h[t] = 0;
    __syncthreads();
    int lo = blockIdx.x * 2048;
    for (int j = t; j < 2048; j += 256) {
        int i = lo + j;
        int p = ((src[i] & 15) << 4) | (tgt[i] & 15);
        atomicAdd(&h[p], 1);
    }
    __syncthreads();
    g_histcta[blockIdx.x * NPAIR + t] = h[t];
}

// ------------------------------ 2: precompute E + bias (CTA 0 also scans) ----------
// E = dec@enc - I = E_d + E_e + E_d@E_e  (E_d@E_e via one bf16 MMA chain,
// E_e stored row-major and read with ldmatrix.trans -> conflict-free).
__global__ void __launch_bounds__(256, 1)
k_precomp(const float* __restrict__ enc, const float* __restrict__ dec,
          const float* __restrict__ cpar, const float* __restrict__ dpar) {
    extern __shared__ char smem[];
    uint32_t sb = smem_u32(smem);
    int tid = threadIdx.x, wid = tid >> 5, lane = tid & 31;
    int wm = wid & 3, wn = wid >> 2;
    int p = blockIdx.x, s = p >> 4, t = p & 15;

    // --- CTA 0: 256-bin scan + per-hist-CTA bases (uses smem before tiles) ---
    if (blockIdx.x == 0) {
        int* ss = (int*)smem;
        int tot = 0;
        for (int c = 0; c < HCTA; c++) tot += g_histcta[c * NPAIR + tid];
        ss[tid] = tot;
        __syncthreads();
        for (int d = 1; d < NPAIR; d <<= 1) {
            int add = (tid >= d) ? ss[tid - d] : 0;
            __syncthreads();
            ss[tid] += add;
            __syncthreads();
        }
        int excl = ss[tid] - tot;
        g_count[tid]  = tot;
        g_offset[tid] = excl;
        int run = excl;
        for (int c = 0; c < HCTA; c++) {
            g_base[c * NPAIR + tid] = run;
            run += g_histcta[c * NPAIR + tid];
        }
        __syncthreads();   // scan smem dead before tile reuse
    }

    const float* decT = dec + (size_t)t * DIMK * DIMK;
    const float* encS = enc + (size_t)s * DIMK * DIMK;

    // E_d = dec - I -> [i][k] bf16 tile at P_A
    {
        const float4* d4 = (const float4*)decT;
        #pragma unroll
        for (int it = 0; it < 16; it++) {
            int idx = it * 256 + tid;
            int d = idx >> 5, r4 = idx & 31;
            float4 v = __ldg(d4 + idx);
            int rb = r4 * 4;
            if (d == rb + 0) v.x -= 1.f;
            if (d == rb + 1) v.y -= 1.f;
            if (d == rb + 2) v.z -= 1.f;
            if (d == rb + 3) v.w -= 1.f;
            __nv_bfloat162 b01 = __floats2bfloat162_rn(v.x, v.y);
            __nv_bfloat162 b23 = __floats2bfloat162_rn(v.z, v.w);
            uint2 u; u.x = reinterpret_cast<uint32_t&>(b01); u.y = reinterpret_cast<uint32_t&>(b23);
            *(uint2*)(smem + P_A + d * TSTRIDE + r4 * 8) = u;
        }
    }
    // E_e = enc - I -> ROW-major [k][n] at P_B (conflict-free stores; ldsm.trans reads)
    {
        const float4* e4 = (const float4*)encS;
        #pragma unroll
        for (int it = 0; it < 16; it++) {
            int idx = it * 256 + tid;
            int r = idx >> 5, c4 = idx & 31;
            float4 v = __ldg(e4 + idx);
            int cb = c4 * 4;
            if (r == cb + 0) v.x -= 1.f;
            if (r == cb + 1) v.y -= 1.f;
            if (r == cb + 2) v.z -= 1.f;
            if (r == cb + 3) v.w -= 1.f;
            __nv_bfloat162 b01 = __floats2bfloat162_rn(v.x, v.y);
            __nv_bfloat162 b23 = __floats2bfloat162_rn(v.z, v.w);
            uint2 u; u.x = reinterpret_cast<uint32_t&>(b01); u.y = reinterpret_cast<uint32_t&>(b23);
            *(uint2*)(smem + P_B + r * TSTRIDE + c4 * 8) = u;
        }
    }
    __syncthreads();

    // E_d @ E_e : 8 warps = 4(M) x 2(N)
    float pacc[2][8][4];
    #pragma unroll
    for (int mt = 0; mt < 2; mt++)
        #pragma unroll
        for (int nt = 0; nt < 8; nt++)
            #pragma unroll
            for (int i = 0; i < 4; i++) pacc[mt][nt][i] = 0.f;

    #pragma unroll
    for (int ks = 0; ks < 8; ks++) {
        int kb = ks * 16;
        uint32_t a[2][4];
        #pragma unroll
        for (int mt = 0; mt < 2; mt++) {
            uint32_t row = wm * 32 + mt * 16 + (lane & 15);
            ldsm_x4(a[mt], sb + P_A + row * TSTRIDE + kb * 2 + ((lane >> 4) << 4));
        }
        #pragma unroll
        for (int j = 0; j < 4; j++) {
            uint32_t n0 = wn * 64 + j * 16;
            uint32_t adr = sb + P_B
                + (kb + (lane & 7) + ((lane >> 4) & 1) * 8) * TSTRIDE
                + (n0 + ((lane >> 3) & 1) * 8) * 2;
            uint32_t q[4];
            ldsm_x4t(q, adr);
            uint32_t b0[2] = {q[0], q[2]}, b1[2] = {q[1], q[3]};
            #pragma unroll
            for (int mt = 0; mt < 2; mt++) {
                mma_bf16(pacc[mt][j * 2 + 0], a[mt], b0);
                mma_bf16(pacc[mt][j * 2 + 1], a[mt], b1);
            }
        }
    }

    // E = pacc + dec + enc - 2I -> global bf16
    int gid = lane >> 2, tig = lane & 3;
    __nv_bfloat16* Ep = g_E + (size_t)p * DIMK * DIMK;
    #pragma unroll
    for (int mt = 0; mt < 2; mt++) {
        #pragma unroll
        for (int nt = 0; nt < 8; nt++) {
            int j = wn * 64 + nt * 8 + tig * 2;
            #pragma unroll
            for (int half = 0; half < 2; half++) {
                int i = wm * 32 + mt * 16 + gid + half * 8;
                float2 dv = *(const float2*)(decT + i * DIMK + j);
                float2 ev = *(const float2*)(encS + i * DIMK + j);
                float w0 = pacc[mt][nt][half * 2 + 0] + dv.x + ev.x - (i == j     ? 2.f : 0.f);
                float w1 = pacc[mt][nt][half * 2 + 1] + dv.y + ev.y - (i == j + 1 ? 2.f : 0.f);
                *(__nv_bfloat162*)(Ep + i * DIMK + j) = __floats2bfloat162_rn(w0, w1);
            }
        }
    }

    // bias = dec @ c + d
    if (tid < DIMK) {
        const float4* drow = (const float4*)(decT + tid * DIMK);
        const float4* cv4  = (const float4*)(cpar + s * DIMK);
        float b = dpar[t * DIMK + tid];
        #pragma unroll
        for (int r4 = 0; r4 < 32; r4++) {
            float4 w = __ldg(drow + r4);
            float4 c = __ldg(cv4 + r4);
            b += w.x * c.x + w.y * c.y + w.z * c.z + w.w * c.w;
        }
        g_bias[p * DIMK + tid] = b;
    }
}

// ------------------------------ 3: single-pass scatter (bases precomputed) ---------
__global__ void k_scatter(const int* __restrict__ src, const int* __restrict__ tgt) {
    __shared__ int h[NPAIR], base[NPAIR];
    int t = threadIdx.x;
    h[t] = 0;
    base[t] = g_base[blockIdx.x * NPAIR + t];
    __syncthreads();
    int lo = blockIdx.x * 2048;
    for (int j = t; j < 2048; j += 256) {
        int i = lo + j;
        int p = ((src[i] & 15) << 4) | (tgt[i] & 15);
        int r = atomicAdd(&h[p], 1);
        g_perm[base[p] + r] = i;
    }
}

// ------------------------------ 4: main grouped GEMM ------------------------------
// out[row,:] = z + z@E^T + bias, rows grouped by pair. 2-chain split-bf16 (z_hi, z_lo).
__global__ void __launch_bounds__(256, 2)
k_main(const float* __restrict__ Z, float* __restrict__ Y) {
    extern __shared__ char smem[];
    uint32_t sb = smem_u32(smem);
    int tid = threadIdx.x, wid = tid >> 5, lane = tid & 31;
    int wm = wid & 1, wn = wid >> 1;
    int p = blockIdx.x / TPP, t0 = blockIdx.x % TPP;

    int cnt = g_count[p], off = g_offset[p];
    if (t0 * 64 >= cnt) return;

    float* sbias = (float*)(smem + S_BIAS);
    int*   sperm = (int*)(smem + S_PERM);
    if (tid < 128) sbias[tid] = g_bias[p * DIMK + tid];

    // E tile via cp.async
    {
        const __nv_bfloat16* Ep = g_E + (size_t)p * DIMK * DIMK;
        #pragma unroll
        for (int it = 0; it < 8; it++) {
            int id = it * 256 + tid;
            int row = id >> 4, c = id & 15;
            cpasync16(sb + S_B + row * TSTRIDE + c * 16, Ep + row * DIMK + c * 8);
        }
    }
    // first stage: raw fp32 z rows
    {
        int base = off + t0 * 64;
        int rows = cnt - t0 * 64; if (rows > 64) rows = 64;
        #pragma unroll
        for (int it = 0; it < 8; it++) {
            int idx = it * 256 + tid;
            int r = idx >> 5, c4 = idx & 31;
            int rr = (r < rows) ? r : 0;
            int grow = __ldg(&g_perm[base + rr]);
            cpasync16(sb + S_STAGE + r * 512 + c4 * 16, Z + (size_t)grow * DIMK + c4 * 4);
        }
    }
    asm volatile("cp.async.commit_group;");

    for (int t = t0; t * 64 < cnt; t += TPP) {
        int base = off + t * 64;
        int rows = cnt - t * 64; if (rows > 64) rows = 64;

        asm volatile("cp.async.wait_group 0;" ::: "memory");
        __syncthreads();

        if (tid < 64) sperm[tid] = g_perm[base + ((tid < 64 && tid < rows) ? tid : 0)];

        // convert stage fp32 -> split bf16 A tiles
        #pragma unroll
        for (int it = 0; it < 8; it++) {
            int idx = it * 256 + tid;
            int r = idx >> 5, c4 = idx & 31;
            float4 v = *(const float4*)(smem + S_STAGE + r * 512 + c4 * 16);
            uint2 hi, lo; split4(v, hi, lo);
            *(uint2*)(smem + S_AHI + r * TSTRIDE + c4 * 8) = hi;
            *(uint2*)(smem + S_ALO + r * TSTRIDE + c4 * 8) = lo;
        }
        __syncthreads();

        // prefetch next tile (overlaps MMA + epilogue)
        int tn = t + TPP;
        if (tn * 64 < cnt) {
            int basen = off + tn * 64;
            int rowsn = cnt - tn * 64; if (rowsn > 64) rowsn = 64;
            #pragma unroll
            for (int it = 0; it < 8; it++) {
                int idx = it * 256 + tid;
                int r = idx >> 5, c4 = idx & 31;
                int rr = (r < rowsn) ? r : 0;
                int grow = __ldg(&g_perm[basen + rr]);
                cpasync16(sb + S_STAGE + r * 512 + c4 * 16, Z + (size_t)grow * DIMK + c4 * 4);
            }
            asm volatile("cp.async.commit_group;");
        }

        // MMA: 2 chains x 8 k-steps
        float acc[2][4][4];
        #pragma unroll
        for (int mt = 0; mt < 2; mt++)
            #pragma unroll
            for (int nt = 0; nt < 4; nt++)
                #pragma unroll
                for (int i = 0; i < 4; i++) acc[mt][nt][i] = 0.f;

        #pragma unroll
        for (int ks = 0; ks < 8; ks++) {
            int kb = ks * 16;
            uint32_t ah[2][4], al[2][4];
            #pragma unroll
            for (int mt = 0; mt < 2; mt++) {
                uint32_t row = wm * 32 + mt * 16 + (lane & 15);
                uint32_t o = row * TSTRIDE + kb * 2 + ((lane >> 4) << 4);
                ldsm_x4(ah[mt], sb + S_AHI + o);
                ldsm_x4(al[mt], sb + S_ALO + o);
            }
            #pragma unroll
            for (int j = 0; j < 2; j++) {
                uint32_t n = wn * 32 + j * 16 + (lane & 15);
                uint32_t o = n * TSTRIDE + kb * 2 + ((lane >> 4) << 4);
                uint32_t qh[4];
                ldsm_x4(qh, sb + S_B + o);
                uint32_t b0[2] = {qh[0], qh[2]}, b1[2] = {qh[1], qh[3]};
                #pragma unroll
                for (int mt = 0; mt < 2; mt++) {
                    mma_bf16(acc[mt][j * 2 + 0], ah[mt], b0);
                    mma_bf16(acc[mt][j * 2 + 0], al[mt], b0);
                    mma_bf16(acc[mt][j * 2 + 1], ah[mt], b1);
                    mma_bf16(acc[mt][j * 2 + 1], al[mt], b1);
                }
            }
        }

        // epilogue: out = acc + z (hi+lo) + bias; scatter
        int gid = lane >> 2, tig = lane & 3;
        #pragma unroll
        for (int mt = 0; mt < 2; mt++) {
            int m0 = wm * 32 + mt * 16 + gid;
            #pragma unroll
            for (int half = 0; half < 2; half++) {
                int m = m0 + half * 8;
                if (m >= rows) continue;
                long gr = (long)sperm[m];
                #pragma unroll
                for (int nt = 0; nt < 4; nt++) {
                    int n = wn * 32 + nt * 8 + tig * 2;
                    __nv_bfloat162 zh = *(const __nv_bfloat162*)(smem + S_AHI + m * TSTRIDE + n * 2);
                    __nv_bfloat162 zl = *(const __nv_bfloat162*)(smem + S_ALO + m * TSTRIDE + n * 2);
                    float2 zhf = __bfloat1622float2(zh);
                    float2 zlf = __bfloat1622float2(zl);
                    float2 o;
                    o.x = acc[mt][nt][half * 2 + 0] + zhf.x + zlf.x + sbias[n];
                    o.y = acc[mt][nt][half * 2 + 1] + zhf.y + zlf.y + sbias[n + 1];
                    *(float2*)(Y + gr * DIMK + n) = o;
                }
            }
        }
    }
}

// ------------------------------ launch ------------------------------
extern "C" void kernel_launch(void* const* d_in, const int* in_sizes, int n_in,
                              void* d_out, int out_size) {
    const float* z    = (const float*)d_in[0];
    const int*   src  = (const int*)  d_in[1];
    const int*   tgt  = (const int*)  d_in[2];
    const float* enc  = (const float*)d_in[3];
    const float* dec  = (const float*)d_in[4];
    const float* cpar = (const float*)d_in[5];
    const float* dpar = (const float*)d_in[6];
    float* out = (float*)d_out;

    cudaFuncSetAttribute(k_precomp, cudaFuncAttributeMaxDynamicSharedMemorySize, PRE_SMEM);
    cudaFuncSetAttribute(k_main,    cudaFuncAttributeMaxDynamicSharedMemorySize, MAIN_SMEM);

    k_hist<<<HCTA, 256>>>(src, tgt);                                  // idx 0
    k_precomp<<<NPAIR, 256, PRE_SMEM>>>(enc, dec, cpar, dpar);        // idx 1 (+scan in CTA0)
    k_scatter<<<HCTA, 256>>>(src, tgt);                               // idx 2
    k_main<<<NPAIR * TPP, 256, MAIN_SMEM>>>(z, out);                  // idx 3 <- profiled
}

// round 7
// speedup vs baseline: 1.1688x; 1.0374x over previous
#include <cuda_runtime.h>
#include <cuda_bf16.h>
#include <cstdint>

#define NCH   16
#define NPAIR 256
#define DIMK  128
#define NB    131072
#define TPP   2
#define HCTA  128                             // histogram/scatter CTAs (1024 rows each)
#define TSTRIDE 272

// ---- k_main smem layout ----
#define S_BIAS   0
#define S_PERM   512
#define S_STAGE  1024                         // 64 x 512B fp32 stage
#define S_AHI    (S_STAGE + 64 * 512)
#define S_ALO    (S_AHI + 64 * TSTRIDE)
#define S_B      (S_ALO + 64 * TSTRIDE)
#define MAIN_SMEM (S_B + 128 * TSTRIDE)       // ~103.4 KB -> 2 CTAs/SM

// ---- precompute smem layout ----
#define P_A     0
#define P_B     (128 * TSTRIDE)
#define PRE_SMEM (2 * 128 * TSTRIDE)          // 69632 B

// ---- scratch ----
__device__ __align__(16) __nv_bfloat16 g_E[(size_t)NPAIR * DIMK * DIMK];  // Wc - I
__device__ float g_bias[NPAIR * DIMK];
__device__ int   g_perm[NB];
__device__ unsigned char g_code[NB];
__device__ int   g_histcta[HCTA * NPAIR];
__device__ int   g_base[HCTA * NPAIR];
__device__ int   g_count[NPAIR];
__device__ int   g_offset[NPAIR];

// ------------------------------ helpers ------------------------------
static __device__ __forceinline__ uint32_t smem_u32(const void* p) {
    uint32_t a;
    asm("{ .reg .u64 t; cvta.to.shared.u64 t, %1; cvt.u32.u64 %0, t; }" : "=r"(a) : "l"(p));
    return a;
}
static __device__ __forceinline__ void split4(float4 v, uint2& hi, uint2& lo) {
    __nv_bfloat162 h01 = __floats2bfloat162_rn(v.x, v.y);
    __nv_bfloat162 h23 = __floats2bfloat162_rn(v.z, v.w);
    float2 f01 = __bfloat1622float2(h01);
    float2 f23 = __bfloat1622float2(h23);
    __nv_bfloat162 l01 = __floats2bfloat162_rn(v.x - f01.x, v.y - f01.y);
    __nv_bfloat162 l23 = __floats2bfloat162_rn(v.z - f23.x, v.w - f23.y);
    hi.x = reinterpret_cast<uint32_t&>(h01); hi.y = reinterpret_cast<uint32_t&>(h23);
    lo.x = reinterpret_cast<uint32_t&>(l01); lo.y = reinterpret_cast<uint32_t&>(l23);
}
static __device__ __forceinline__ void ldsm_x4(uint32_t* r, uint32_t a) {
    asm volatile("ldmatrix.sync.aligned.m8n8.x4.shared.b16 {%0,%1,%2,%3}, [%4];"
        : "=r"(r[0]), "=r"(r[1]), "=r"(r[2]), "=r"(r[3]) : "r"(a));
}
static __device__ __forceinline__ void ldsm_x4t(uint32_t* r, uint32_t a) {
    asm volatile("ldmatrix.sync.aligned.m8n8.x4.trans.shared.b16 {%0,%1,%2,%3}, [%4];"
        : "=r"(r[0]), "=r"(r[1]), "=r"(r[2]), "=r"(r[3]) : "r"(a));
}
static __device__ __forceinline__ void mma_bf16(float* d, const uint32_t* a, const uint32_t* b) {
    asm volatile(
        "mma.sync.aligned.m16n8k16.row.col.f32.bf16.bf16.f32 "
        "{%0,%1,%2,%3}, {%4,%5,%6,%7}, {%8,%9}, {%0,%1,%2,%3};"
        : "+f"(d[0]), "+f"(d[1]), "+f"(d[2]), "+f"(d[3])
        : "r"(a[0]), "r"(a[1]), "r"(a[2]), "r"(a[3]), "r"(b[0]), "r"(b[1]));
}
static __device__ __forceinline__ void cpasync16(uint32_t dst, const void* src) {
    asm volatile("cp.async.ca.shared.global [%0], [%1], 16;" :: "r"(dst), "l"(src));
}

// ------------------------------ 1: per-CTA histogram + code cache ------------------
__global__ void k_hist(const int* __restrict__ src, const int* __restrict__ tgt) {
    __shared__ int h[NPAIR];
    int t = threadIdx.x;
    h[t] = 0;
    __syncthreads();
    int lo = blockIdx.x * 1024;
    for (int j = t; j < 1024; j += 256) {
        int i = lo + j;
        int p = ((src[i] & 15) << 4) | (tgt[i] & 15);
        g_code[i] = (unsigned char)p;
        atomicAdd(&h[p], 1);
    }
    __syncthreads();
    g_histcta[blockIdx.x * NPAIR + t] = h[t];
}

// ------------------------------ 2: precompute E + bias (CTA 0 also scans) ----------
__global__ void __launch_bounds__(256, 1)
k_precomp(const float* __restrict__ enc, const float* __restrict__ dec,
          const float* __restrict__ cpar, const float* __restrict__ dpar) {
    extern __shared__ char smem[];
    uint32_t sb = smem_u32(smem);
    int tid = threadIdx.x, wid = tid >> 5, lane = tid & 31;
    int wm = wid & 3, wn = wid >> 2;
    int p = blockIdx.x, s = p >> 4, t = p & 15;

    if (blockIdx.x == 0) {
        int* ss = (int*)smem;
        int tot = 0;
        for (int c = 0; c < HCTA; c++) tot += g_histcta[c * NPAIR + tid];
        ss[tid] = tot;
        __syncthreads();
        for (int d = 1; d < NPAIR; d <<= 1) {
            int add = (tid >= d) ? ss[tid - d] : 0;
            __syncthreads();
            ss[tid] += add;
            __syncthreads();
        }
        int excl = ss[tid] - tot;
        g_count[tid]  = tot;
        g_offset[tid] = excl;
        int run = excl;
        for (int c = 0; c < HCTA; c++) {
            g_base[c * NPAIR + tid] = run;
            run += g_histcta[c * NPAIR + tid];
        }
        __syncthreads();
    }

    const float* decT = dec + (size_t)t * DIMK * DIMK;
    const float* encS = enc + (size_t)s * DIMK * DIMK;

    // E_d = dec - I -> [i][k] bf16 tile at P_A
    {
        const float4* d4 = (const float4*)decT;
        #pragma unroll
        for (int it = 0; it < 16; it++) {
            int idx = it * 256 + tid;
            int d = idx >> 5, r4 = idx & 31;
            float4 v = __ldg(d4 + idx);
            int rb = r4 * 4;
            if (d == rb + 0) v.x -= 1.f;
            if (d == rb + 1) v.y -= 1.f;
            if (d == rb + 2) v.z -= 1.f;
            if (d == rb + 3) v.w -= 1.f;
            __nv_bfloat162 b01 = __floats2bfloat162_rn(v.x, v.y);
            __nv_bfloat162 b23 = __floats2bfloat162_rn(v.z, v.w);
            uint2 u; u.x = reinterpret_cast<uint32_t&>(b01); u.y = reinterpret_cast<uint32_t&>(b23);
            *(uint2*)(smem + P_A + d * TSTRIDE + r4 * 8) = u;
        }
    }
    // E_e = enc - I -> ROW-major [k][n] at P_B (conflict-free; ldsm.trans reads)
    {
        const float4* e4 = (const float4*)encS;
        #pragma unroll
        for (int it = 0; it < 16; it++) {
            int idx = it * 256 + tid;
            int r = idx >> 5, c4 = idx & 31;
            float4 v = __ldg(e4 + idx);
            int cb = c4 * 4;
            if (r == cb + 0) v.x -= 1.f;
            if (r == cb + 1) v.y -= 1.f;
            if (r == cb + 2) v.z -= 1.f;
            if (r == cb + 3) v.w -= 1.f;
            __nv_bfloat162 b01 = __floats2bfloat162_rn(v.x, v.y);
            __nv_bfloat162 b23 = __floats2bfloat162_rn(v.z, v.w);
            uint2 u; u.x = reinterpret_cast<uint32_t&>(b01); u.y = reinterpret_cast<uint32_t&>(b23);
            *(uint2*)(smem + P_B + r * TSTRIDE + c4 * 8) = u;
        }
    }
    __syncthreads();

    float pacc[2][8][4];
    #pragma unroll
    for (int mt = 0; mt < 2; mt++)
        #pragma unroll
        for (int nt = 0; nt < 8; nt++)
            #pragma unroll
            for (int i = 0; i < 4; i++) pacc[mt][nt][i] = 0.f;

    #pragma unroll
    for (int ks = 0; ks < 8; ks++) {
        int kb = ks * 16;
        uint32_t a[2][4];
        #pragma unroll
        for (int mt = 0; mt < 2; mt++) {
            uint32_t row = wm * 32 + mt * 16 + (lane & 15);
            ldsm_x4(a[mt], sb + P_A + row * TSTRIDE + kb * 2 + ((lane >> 4) << 4));
        }
        #pragma unroll
        for (int j = 0; j < 4; j++) {
            uint32_t n0 = wn * 64 + j * 16;
            uint32_t adr = sb + P_B
                + (kb + (lane & 7) + ((lane >> 4) & 1) * 8) * TSTRIDE
                + (n0 + ((lane >> 3) & 1) * 8) * 2;
            uint32_t q[4];
            ldsm_x4t(q, adr);
            uint32_t b0[2] = {q[0], q[2]}, b1[2] = {q[1], q[3]};
            #pragma unroll
            for (int mt = 0; mt < 2; mt++) {
                mma_bf16(pacc[mt][j * 2 + 0], a[mt], b0);
                mma_bf16(pacc[mt][j * 2 + 1], a[mt], b1);
            }
        }
    }

    // E = pacc + dec + enc - 2I -> global bf16
    int gid = lane >> 2, tig = lane & 3;
    __nv_bfloat16* Ep = g_E + (size_t)p * DIMK * DIMK;
    #pragma unroll
    for (int mt = 0; mt < 2; mt++) {
        #pragma unroll
        for (int nt = 0; nt < 8; nt++) {
            int j = wn * 64 + nt * 8 + tig * 2;
            #pragma unroll
            for (int half = 0; half < 2; half++) {
                int i = wm * 32 + mt * 16 + gid + half * 8;
                float2 dv = *(const float2*)(decT + i * DIMK + j);
                float2 ev = *(const float2*)(encS + i * DIMK + j);
                float w0 = pacc[mt][nt][half * 2 + 0] + dv.x + ev.x - (i == j     ? 2.f : 0.f);
                float w1 = pacc[mt][nt][half * 2 + 1] + dv.y + ev.y - (i == j + 1 ? 2.f : 0.f);
                *(__nv_bfloat162*)(Ep + i * DIMK + j) = __floats2bfloat162_rn(w0, w1);
            }
        }
    }

    // bias = dec @ c + d
    if (tid < DIMK) {
        const float4* drow = (const float4*)(decT + tid * DIMK);
        const float4* cv4  = (const float4*)(cpar + s * DIMK);
        float b = dpar[t * DIMK + tid];
        #pragma unroll
        for (int r4 = 0; r4 < 32; r4++) {
            float4 w = __ldg(drow + r4);
            float4 c = __ldg(cv4 + r4);
            b += w.x * c.x + w.y * c.y + w.z * c.z + w.w * c.w;
        }
        g_bias[p * DIMK + tid] = b;
    }
}

// ------------------------------ 3: single-pass scatter (codes cached) --------------
__global__ void k_scatter() {
    __shared__ int h[NPAIR], base[NPAIR];
    int t = threadIdx.x;
    h[t] = 0;
    base[t] = g_base[blockIdx.x * NPAIR + t];
    __syncthreads();
    int lo = blockIdx.x * 1024;
    for (int j = t; j < 1024; j += 256) {
        int p = g_code[lo + j];
        int r = atomicAdd(&h[p], 1);
        g_perm[base[p] + r] = lo + j;
    }
}

// ------------------------------ 4: main grouped GEMM ------------------------------
// out[row,:] = z + z_hi@E^T + bias (z_lo@E dropped: ~1.6e-4 rms, budgeted).
// z passthrough stays exact via hi+lo reconstruction in the epilogue.
__global__ void __launch_bounds__(256, 2)
k_main(const float* __restrict__ Z, float* __restrict__ Y) {
    extern __shared__ char smem[];
    uint32_t sb = smem_u32(smem);
    int tid = threadIdx.x, wid = tid >> 5, lane = tid & 31;
    int wm = wid & 1, wn = wid >> 1;
    int p = blockIdx.x / TPP, t0 = blockIdx.x % TPP;

    int cnt = g_count[p], off = g_offset[p];
    if (t0 * 64 >= cnt) return;

    float* sbias = (float*)(smem + S_BIAS);
    int*   sperm = (int*)(smem + S_PERM);
    if (tid < 128) sbias[tid] = g_bias[p * DIMK + tid];

    // E tile via cp.async
    {
        const __nv_bfloat16* Ep = g_E + (size_t)p * DIMK * DIMK;
        #pragma unroll
        for (int it = 0; it < 8; it++) {
            int id = it * 256 + tid;
            int row = id >> 4, c = id & 15;
            cpasync16(sb + S_B + row * TSTRIDE + c * 16, Ep + row * DIMK + c * 8);
        }
    }
    // first stage: raw fp32 z rows
    {
        int base = off + t0 * 64;
        int rows = cnt - t0 * 64; if (rows > 64) rows = 64;
        #pragma unroll
        for (int it = 0; it < 8; it++) {
            int idx = it * 256 + tid;
            int r = idx >> 5, c4 = idx & 31;
            int rr = (r < rows) ? r : 0;
            int grow = __ldg(&g_perm[base + rr]);
            cpasync16(sb + S_STAGE + r * 512 + c4 * 16, Z + (size_t)grow * DIMK + c4 * 4);
        }
    }
    asm volatile("cp.async.commit_group;");

    for (int t = t0; t * 64 < cnt; t += TPP) {
        int base = off + t * 64;
        int rows = cnt - t * 64; if (rows > 64) rows = 64;

        asm volatile("cp.async.wait_group 0;" ::: "memory");
        __syncthreads();

        if (tid < 64) sperm[tid] = g_perm[base + ((tid < rows) ? tid : 0)];

        // convert stage fp32 -> split bf16 A tiles (lo kept for exact epilogue z)
        #pragma unroll
        for (int it = 0; it < 8; it++) {
            int idx = it * 256 + tid;
            int r = idx >> 5, c4 = idx & 31;
            float4 v = *(const float4*)(smem + S_STAGE + r * 512 + c4 * 16);
            uint2 hi, lo; split4(v, hi, lo);
            *(uint2*)(smem + S_AHI + r * TSTRIDE + c4 * 8) = hi;
            *(uint2*)(smem + S_ALO + r * TSTRIDE + c4 * 8) = lo;
        }
        __syncthreads();

        // prefetch next tile (overlaps MMA + epilogue)
        int tn = t + TPP;
        if (tn * 64 < cnt) {
            int basen = off + tn * 64;
            int rowsn = cnt - tn * 64; if (rowsn > 64) rowsn = 64;
            #pragma unroll
            for (int it = 0; it < 8; it++) {
                int idx = it * 256 + tid;
                int r = idx >> 5, c4 = idx & 31;
                int rr = (r < rowsn) ? r : 0;
                int grow = __ldg(&g_perm[basen + rr]);
                cpasync16(sb + S_STAGE + r * 512 + c4 * 16, Z + (size_t)grow * DIMK + c4 * 4);
            }
            asm volatile("cp.async.commit_group;");
        }

        // MMA: single z_hi chain x 8 k-steps
        float acc[2][4][4];
        #pragma unroll
        for (int mt = 0; mt < 2; mt++)
            #pragma unroll
            for (int nt = 0; nt < 4; nt++)
                #pragma unroll
                for (int i = 0; i < 4; i++) acc[mt][nt][i] = 0.f;

        #pragma unroll
        for (int ks = 0; ks < 8; ks++) {
            int kb = ks * 16;
            uint32_t ah[2][4];
            #pragma unroll
            for (int mt = 0; mt < 2; mt++) {
                uint32_t row = wm * 32 + mt * 16 + (lane & 15);
                uint32_t o = row * TSTRIDE + kb * 2 + ((lane >> 4) << 4);
                ldsm_x4(ah[mt], sb + S_AHI + o);
            }
            #pragma unroll
            for (int j = 0; j < 2; j++) {
                uint32_t n = wn * 32 + j * 16 + (lane & 15);
                uint32_t o = n * TSTRIDE + kb * 2 + ((lane >> 4) << 4);
                uint32_t qh[4];
                ldsm_x4(qh, sb + S_B + o);
                uint32_t b0[2] = {qh[0], qh[2]}, b1[2] = {qh[1], qh[3]};
                #pragma unroll
                for (int mt = 0; mt < 2; mt++) {
                    mma_bf16(acc[mt][j * 2 + 0], ah[mt], b0);
                    mma_bf16(acc[mt][j * 2 + 1], ah[mt], b1);
                }
            }
        }

        // epilogue: out = acc + z (hi+lo) + bias; scatter
        int gid = lane >> 2, tig = lane & 3;
        #pragma unroll
        for (int mt = 0; mt < 2; mt++) {
            int m0 = wm * 32 + mt * 16 + gid;
            #pragma unroll
            for (int half = 0; half < 2; half++) {
                int m = m0 + half * 8;
                if (m >= rows) continue;
                long gr = (long)sperm[m];
                #pragma unroll
                for (int nt = 0; nt < 4; nt++) {
                    int n = wn * 32 + nt * 8 + tig * 2;
                    __nv_bfloat162 zh = *(const __nv_bfloat162*)(smem + S_AHI + m * TSTRIDE + n * 2);
                    __nv_bfloat162 zl = *(const __nv_bfloat162*)(smem + S_ALO + m * TSTRIDE + n * 2);
                    float2 zhf = __bfloat1622float2(zh);
                    float2 zlf = __bfloat1622float2(zl);
                    float2 o;
                    o.x = acc[mt][nt][half * 2 + 0] + zhf.x + zlf.x + sbias[n];
                    o.y = acc[mt][nt][half * 2 + 1] + zhf.y + zlf.y + sbias[n + 1];
                    *(float2*)(Y + gr * DIMK + n) = o;
                }
            }
        }
    }
}

// ------------------------------ launch ------------------------------
extern "C" void kernel_launch(void* const* d_in, const int* in_sizes, int n_in,
                              void* d_out, int out_size) {
    const float* z    = (const float*)d_in[0];
    const int*   src  = (const int*)  d_in[1];
    const int*   tgt  = (const int*)  d_in[2];
    const float* enc  = (const float*)d_in[3];
    const float* dec  = (const float*)d_in[4];
    const float* cpar = (const float*)d_in[5];
    const float* dpar = (const float*)d_in[6];
    float* out = (float*)d_out;

    cudaFuncSetAttribute(k_precomp, cudaFuncAttributeMaxDynamicSharedMemorySize, PRE_SMEM);
    cudaFuncSetAttribute(k_main,    cudaFuncAttributeMaxDynamicSharedMemorySize, MAIN_SMEM);

    k_hist<<<HCTA, 256>>>(src, tgt);                                  // idx 0
    k_precomp<<<NPAIR, 256, PRE_SMEM>>>(enc, dec, cpar, dpar);        // idx 1 (+scan in CTA0)
    k_scatter<<<HCTA, 256>>>();                                       // idx 2
    k_main<<<NPAIR * TPP, 256, MAIN_SMEM>>>(z, out);                  // idx 3 <- profiled
}

// round 8
// speedup vs baseline: 1.3312x; 1.1389x over previous
#include <cuda_runtime.h>
#include <cuda_bf16.h>
#include <cstdint>

#define NCH   16
#define NPAIR 256
#define DIMK  128
#define NB    131072
#define TPP   4
#define HCTA  128                             // histogram/scatter CTAs (1024 rows each)
#define TSTRIDE 272

// ---- k_main smem layout (no fp32 stage -> 70.7 KB -> 3 CTAs/SM) ----
#define S_BIAS   0
#define S_PERM   512
#define S_AHI    1024
#define S_ALO    (S_AHI + 64 * TSTRIDE)
#define S_B      (S_ALO + 64 * TSTRIDE)
#define MAIN_SMEM (S_B + 128 * TSTRIDE)       // 70656 B

// ---- precompute smem layout ----
#define P_A     0
#define P_B     (128 * TSTRIDE)
#define PRE_SMEM (2 * 128 * TSTRIDE)          // 69632 B

// ---- scratch ----
__device__ __align__(16) __nv_bfloat16 g_E[(size_t)NPAIR * DIMK * DIMK];  // Wc - I
__device__ float g_bias[NPAIR * DIMK];
__device__ int   g_perm[NB];
__device__ unsigned char g_code[NB];
__device__ int   g_histcta[HCTA * NPAIR];
__device__ int   g_base[HCTA * NPAIR];
__device__ int   g_count[NPAIR];
__device__ int   g_offset[NPAIR];

// ------------------------------ helpers ------------------------------
static __device__ __forceinline__ uint32_t smem_u32(const void* p) {
    uint32_t a;
    asm("{ .reg .u64 t; cvta.to.shared.u64 t, %1; cvt.u32.u64 %0, t; }" : "=r"(a) : "l"(p));
    return a;
}
static __device__ __forceinline__ void split4(float4 v, uint2& hi, uint2& lo) {
    __nv_bfloat162 h01 = __floats2bfloat162_rn(v.x, v.y);
    __nv_bfloat162 h23 = __floats2bfloat162_rn(v.z, v.w);
    float2 f01 = __bfloat1622float2(h01);
    float2 f23 = __bfloat1622float2(h23);
    __nv_bfloat162 l01 = __floats2bfloat162_rn(v.x - f01.x, v.y - f01.y);
    __nv_bfloat162 l23 = __floats2bfloat162_rn(v.z - f23.x, v.w - f23.y);
    hi.x = reinterpret_cast<uint32_t&>(h01); hi.y = reinterpret_cast<uint32_t&>(h23);
    lo.x = reinterpret_cast<uint32_t&>(l01); lo.y = reinterpret_cast<uint32_t&>(l23);
}
static __device__ __forceinline__ void ldsm_x4(uint32_t* r, uint32_t a) {
    asm volatile("ldmatrix.sync.aligned.m8n8.x4.shared.b16 {%0,%1,%2,%3}, [%4];"
        : "=r"(r[0]), "=r"(r[1]), "=r"(r[2]), "=r"(r[3]) : "r"(a));
}
static __device__ __forceinline__ void ldsm_x4t(uint32_t* r, uint32_t a) {
    asm volatile("ldmatrix.sync.aligned.m8n8.x4.trans.shared.b16 {%0,%1,%2,%3}, [%4];"
        : "=r"(r[0]), "=r"(r[1]), "=r"(r[2]), "=r"(r[3]) : "r"(a));
}
static __device__ __forceinline__ void mma_bf16(float* d, const uint32_t* a, const uint32_t* b) {
    asm volatile(
        "mma.sync.aligned.m16n8k16.row.col.f32.bf16.bf16.f32 "
        "{%0,%1,%2,%3}, {%4,%5,%6,%7}, {%8,%9}, {%0,%1,%2,%3};"
        : "+f"(d[0]), "+f"(d[1]), "+f"(d[2]), "+f"(d[3])
        : "r"(a[0]), "r"(a[1]), "r"(a[2]), "r"(a[3]), "r"(b[0]), "r"(b[1]));
}
static __device__ __forceinline__ void cpasync16(uint32_t dst, const void* src) {
    asm volatile("cp.async.ca.shared.global [%0], [%1], 16;" :: "r"(dst), "l"(src));
}

// ------------------------------ 1: per-CTA histogram + code cache ------------------
__global__ void k_hist(const int* __restrict__ src, const int* __restrict__ tgt) {
    __shared__ int h[NPAIR];
    int t = threadIdx.x;
    h[t] = 0;
    __syncthreads();
    int lo = blockIdx.x * 1024;
    for (int j = t; j < 1024; j += 256) {
        int i = lo + j;
        int p = ((src[i] & 15) << 4) | (tgt[i] & 15);
        g_code[i] = (unsigned char)p;
        atomicAdd(&h[p], 1);
    }
    __syncthreads();
    g_histcta[blockIdx.x * NPAIR + t] = h[t];
}

// ------------------------------ 2: precompute E + bias (CTA 0 also scans) ----------
__global__ void __launch_bounds__(256, 1)
k_precomp(const float* __restrict__ enc, const float* __restrict__ dec,
          const float* __restrict__ cpar, const float* __restrict__ dpar) {
    extern __shared__ char smem[];
    uint32_t sb = smem_u32(smem);
    int tid = threadIdx.x, wid = tid >> 5, lane = tid & 31;
    int wm = wid & 3, wn = wid >> 2;
    int p = blockIdx.x, s = p >> 4, t = p & 15;

    if (blockIdx.x == 0) {
        int* ss = (int*)smem;
        int tot = 0;
        for (int c = 0; c < HCTA; c++) tot += g_histcta[c * NPAIR + tid];
        ss[tid] = tot;
        __syncthreads();
        for (int d = 1; d < NPAIR; d <<= 1) {
            int add = (tid >= d) ? ss[tid - d] : 0;
            __syncthreads();
            ss[tid] += add;
            __syncthreads();
        }
        int excl = ss[tid] - tot;
        g_count[tid]  = tot;
        g_offset[tid] = excl;
        int run = excl;
        for (int c = 0; c < HCTA; c++) {
            g_base[c * NPAIR + tid] = run;
            run += g_histcta[c * NPAIR + tid];
        }
        __syncthreads();
    }

    const float* decT = dec + (size_t)t * DIMK * DIMK;
    const float* encS = enc + (size_t)s * DIMK * DIMK;

    // E_d = dec - I -> [i][k] bf16 tile at P_A
    {
        const float4* d4 = (const float4*)decT;
        #pragma unroll
        for (int it = 0; it < 16; it++) {
            int idx = it * 256 + tid;
            int d = idx >> 5, r4 = idx & 31;
            float4 v = __ldg(d4 + idx);
            int rb = r4 * 4;
            if (d == rb + 0) v.x -= 1.f;
            if (d == rb + 1) v.y -= 1.f;
            if (d == rb + 2) v.z -= 1.f;
            if (d == rb + 3) v.w -= 1.f;
            __nv_bfloat162 b01 = __floats2bfloat162_rn(v.x, v.y);
            __nv_bfloat162 b23 = __floats2bfloat162_rn(v.z, v.w);
            uint2 u; u.x = reinterpret_cast<uint32_t&>(b01); u.y = reinterpret_cast<uint32_t&>(b23);
            *(uint2*)(smem + P_A + d * TSTRIDE + r4 * 8) = u;
        }
    }
    // E_e = enc - I -> ROW-major [k][n] at P_B (conflict-free; ldsm.trans reads)
    {
        const float4* e4 = (const float4*)encS;
        #pragma unroll
        for (int it = 0; it < 16; it++) {
            int idx = it * 256 + tid;
            int r = idx >> 5, c4 = idx & 31;
            float4 v = __ldg(e4 + idx);
            int cb = c4 * 4;
            if (r == cb + 0) v.x -= 1.f;
            if (r == cb + 1) v.y -= 1.f;
            if (r == cb + 2) v.z -= 1.f;
            if (r == cb + 3) v.w -= 1.f;
            __nv_bfloat162 b01 = __floats2bfloat162_rn(v.x, v.y);
            __nv_bfloat162 b23 = __floats2bfloat162_rn(v.z, v.w);
            uint2 u; u.x = reinterpret_cast<uint32_t&>(b01); u.y = reinterpret_cast<uint32_t&>(b23);
            *(uint2*)(smem + P_B + r * TSTRIDE + c4 * 8) = u;
        }
    }
    __syncthreads();

    float pacc[2][8][4];
    #pragma unroll
    for (int mt = 0; mt < 2; mt++)
        #pragma unroll
        for (int nt = 0; nt < 8; nt++)
            #pragma unroll
            for (int i = 0; i < 4; i++) pacc[mt][nt][i] = 0.f;

    #pragma unroll
    for (int ks = 0; ks < 8; ks++) {
        int kb = ks * 16;
        uint32_t a[2][4];
        #pragma unroll
        for (int mt = 0; mt < 2; mt++) {
            uint32_t row = wm * 32 + mt * 16 + (lane & 15);
            ldsm_x4(a[mt], sb + P_A + row * TSTRIDE + kb * 2 + ((lane >> 4) << 4));
        }
        #pragma unroll
        for (int j = 0; j < 4; j++) {
            uint32_t n0 = wn * 64 + j * 16;
            uint32_t adr = sb + P_B
                + (kb + (lane & 7) + ((lane >> 4) & 1) * 8) * TSTRIDE
                + (n0 + ((lane >> 3) & 1) * 8) * 2;
            uint32_t q[4];
            ldsm_x4t(q, adr);
            uint32_t b0[2] = {q[0], q[2]}, b1[2] = {q[1], q[3]};
            #pragma unroll
            for (int mt = 0; mt < 2; mt++) {
                mma_bf16(pacc[mt][j * 2 + 0], a[mt], b0);
                mma_bf16(pacc[mt][j * 2 + 1], a[mt], b1);
            }
        }
    }

    // E = pacc + dec + enc - 2I -> global bf16
    int gid = lane >> 2, tig = lane & 3;
    __nv_bfloat16* Ep = g_E + (size_t)p * DIMK * DIMK;
    #pragma unroll
    for (int mt = 0; mt < 2; mt++) {
        #pragma unroll
        for (int nt = 0; nt < 8; nt++) {
            int j = wn * 64 + nt * 8 + tig * 2;
            #pragma unroll
            for (int half = 0; half < 2; half++) {
                int i = wm * 32 + mt * 16 + gid + half * 8;
                float2 dv = *(const float2*)(decT + i * DIMK + j);
                float2 ev = *(const float2*)(encS + i * DIMK + j);
                float w0 = pacc[mt][nt][half * 2 + 0] + dv.x + ev.x - (i == j     ? 2.f : 0.f);
                float w1 = pacc[mt][nt][half * 2 + 1] + dv.y + ev.y - (i == j + 1 ? 2.f : 0.f);
                *(__nv_bfloat162*)(Ep + i * DIMK + j) = __floats2bfloat162_rn(w0, w1);
            }
        }
    }

    // bias = dec @ c + d
    if (tid < DIMK) {
        const float4* drow = (const float4*)(decT + tid * DIMK);
        const float4* cv4  = (const float4*)(cpar + s * DIMK);
        float b = dpar[t * DIMK + tid];
        #pragma unroll
        for (int r4 = 0; r4 < 32; r4++) {
            float4 w = __ldg(drow + r4);
            float4 c = __ldg(cv4 + r4);
            b += w.x * c.x + w.y * c.y + w.z * c.z + w.w * c.w;
        }
        g_bias[p * DIMK + tid] = b;
    }
}

// ------------------------------ 3: single-pass scatter (codes cached) --------------
__global__ void k_scatter() {
    __shared__ int h[NPAIR], base[NPAIR];
    int t = threadIdx.x;
    h[t] = 0;
    base[t] = g_base[blockIdx.x * NPAIR + t];
    __syncthreads();
    int lo = blockIdx.x * 1024;
    for (int j = t; j < 1024; j += 256) {
        int p = g_code[lo + j];
        int r = atomicAdd(&h[p], 1);
        g_perm[base[p] + r] = lo + j;
    }
}

// ------------------------------ 4: main grouped GEMM ------------------------------
// out[row,:] = z + z_hi@E^T + bias, rows grouped by pair. z passthrough exact (hi+lo).
// No fp32 stage: LDG.128 gather -> split in regs -> STS; 3 CTAs/SM for latency hiding.
__global__ void __launch_bounds__(256, 3)
k_main(const float* __restrict__ Z, float* __restrict__ Y) {
    extern __shared__ char smem[];
    uint32_t sb = smem_u32(smem);
    int tid = threadIdx.x, wid = tid >> 5, lane = tid & 31;
    int wm = wid & 1, wn = wid >> 1;
    int p = blockIdx.x / TPP, t0 = blockIdx.x % TPP;

    int cnt = g_count[p], off = g_offset[p];
    if (t0 * 64 >= cnt) return;

    float* sbias = (float*)(smem + S_BIAS);
    int*   sperm = (int*)(smem + S_PERM);
    if (tid < 128) sbias[tid] = g_bias[p * DIMK + tid];

    // E tile via cp.async (L2-hot; overlaps first gather)
    {
        const __nv_bfloat16* Ep = g_E + (size_t)p * DIMK * DIMK;
        #pragma unroll
        for (int it = 0; it < 8; it++) {
            int id = it * 256 + tid;
            int row = id >> 4, c = id & 15;
            cpasync16(sb + S_B + row * TSTRIDE + c * 16, Ep + row * DIMK + c * 8);
        }
        asm volatile("cp.async.commit_group;");
    }

    bool first = true;
    for (int t = t0; t * 64 < cnt; t += TPP) {
        int base = off + t * 64;
        int rows = cnt - t * 64; if (rows > 64) rows = 64;

        if (!first) __syncthreads();   // prior-iter epilogue reads of A done

        if (tid < 64) sperm[tid] = g_perm[base + ((tid < rows) ? tid : 0)];

        // gather: LDG.128 -> split -> STS (8 float4 per thread, 2 rows)
        #pragma unroll
        for (int it = 0; it < 8; it++) {
            int idx = it * 256 + tid;
            int r = idx >> 5, c4 = idx & 31;
            int rr = (r < rows) ? r : 0;
            int grow = __ldg(&g_perm[base + rr]);
            float4 v = __ldg((const float4*)(Z + (size_t)grow * DIMK) + c4);
            uint2 hi, lo; split4(v, hi, lo);
            *(uint2*)(smem + S_AHI + r * TSTRIDE + c4 * 8) = hi;
            *(uint2*)(smem + S_ALO + r * TSTRIDE + c4 * 8) = lo;
        }
        if (first) { asm volatile("cp.async.wait_group 0;" ::: "memory"); first = false; }
        __syncthreads();

        // MMA: single z_hi chain x 8 k-steps
        float acc[2][4][4];
        #pragma unroll
        for (int mt = 0; mt < 2; mt++)
            #pragma unroll
            for (int nt = 0; nt < 4; nt++)
                #pragma unroll
                for (int i = 0; i < 4; i++) acc[mt][nt][i] = 0.f;

        #pragma unroll
        for (int ks = 0; ks < 8; ks++) {
            int kb = ks * 16;
            uint32_t ah[2][4];
            #pragma unroll
            for (int mt = 0; mt < 2; mt++) {
                uint32_t row = wm * 32 + mt * 16 + (lane & 15);
                uint32_t o = row * TSTRIDE + kb * 2 + ((lane >> 4) << 4);
                ldsm_x4(ah[mt], sb + S_AHI + o);
            }
            #pragma unroll
            for (int j = 0; j < 2; j++) {
                uint32_t n = wn * 32 + j * 16 + (lane & 15);
                uint32_t o = n * TSTRIDE + kb * 2 + ((lane >> 4) << 4);
                uint32_t qh[4];
                ldsm_x4(qh, sb + S_B + o);
                uint32_t b0[2] = {qh[0], qh[2]}, b1[2] = {qh[1], qh[3]};
                #pragma unroll
                for (int mt = 0; mt < 2; mt++) {
                    mma_bf16(acc[mt][j * 2 + 0], ah[mt], b0);
                    mma_bf16(acc[mt][j * 2 + 1], ah[mt], b1);
                }
            }
        }

        // epilogue: out = acc + z (hi+lo) + bias; scatter
        int gid = lane >> 2, tig = lane & 3;
        #pragma unroll
        for (int mt = 0; mt < 2; mt++) {
            int m0 = wm * 32 + mt * 16 + gid;
            #pragma unroll
            for (int half = 0; half < 2; half++) {
                int m = m0 + half * 8;
                if (m >= rows) continue;
                long gr = (long)sperm[m];
                #pragma unroll
                for (int nt = 0; nt < 4; nt++) {
                    int n = wn * 32 + nt * 8 + tig * 2;
                    __nv_bfloat162 zh = *(const __nv_bfloat162*)(smem + S_AHI + m * TSTRIDE + n * 2);
                    __nv_bfloat162 zl = *(const __nv_bfloat162*)(smem + S_ALO + m * TSTRIDE + n * 2);
                    float2 zhf = __bfloat1622float2(zh);
                    float2 zlf = __bfloat1622float2(zl);
                    float2 o;
                    o.x = acc[mt][nt][half * 2 + 0] + zhf.x + zlf.x + sbias[n];
                    o.y = acc[mt][nt][half * 2 + 1] + zhf.y + zlf.y + sbias[n + 1];
                    *(float2*)(Y + gr * DIMK + n) = o;
                }
            }
        }
    }
}

// ------------------------------ launch ------------------------------
extern "C" void kernel_launch(void* const* d_in, const int* in_sizes, int n_in,
                              void* d_out, int out_size) {
    const float* z    = (const float*)d_in[0];
    const int*   src  = (const int*)  d_in[1];
    const int*   tgt  = (const int*)  d_in[2];
    const float* enc  = (const float*)d_in[3];
    const float* dec  = (const float*)d_in[4];
    const float* cpar = (const float*)d_in[5];
    const float* dpar = (const float*)d_in[6];
    float* out = (float*)d_out;

    cudaFuncSetAttribute(k_precomp, cudaFuncAttributeMaxDynamicSharedMemorySize, PRE_SMEM);
    cudaFuncSetAttribute(k_main,    cudaFuncAttributeMaxDynamicSharedMemorySize, MAIN_SMEM);

    k_hist<<<HCTA, 256>>>(src, tgt);                                  // idx 0
    k_precomp<<<NPAIR, 256, PRE_SMEM>>>(enc, dec, cpar, dpar);        // idx 1 (+scan in CTA0)
    k_scatter<<<HCTA, 256>>>();                                       // idx 2
    k_main<<<NPAIR * TPP, 256, MAIN_SMEM>>>(z, out);                  // idx 3 <- profiled
}